// round 7
// baseline (speedup 1.0000x reference)
#include <cuda_runtime.h>

// Fixed problem dims
#define NB 4
#define NQv 512
#define MMv 512
#define DDv 256
#define HHv 256

// Scratch (device globals: no allocations allowed)
__device__ float g_q[NB * NQv * HHv];    // projected q, [b*NQ+n][h]
__device__ float g_kT[NB * HHv * MMv];   // projected k, transposed: [b][h][m]
__device__ float g_sc[NB * NQv * MMv];   // raw scores [b][n][m]

__device__ __forceinline__ float fex2(float x) {
    float y; asm("ex2.approx.f32 %0, %1;" : "=f"(y) : "f"(x)); return y;
}
__device__ __forceinline__ unsigned long long pk2(float a, float b) {
    unsigned long long r; asm("mov.b64 %0, {%1, %2};" : "=l"(r) : "f"(a), "f"(b)); return r;
}
__device__ __forceinline__ void fma2(unsigned long long &d, unsigned long long a, unsigned long long b) {
    asm("fma.rn.f32x2 %0, %1, %2, %0;" : "+l"(d) : "l"(a), "l"(b));
}
__device__ __forceinline__ float2 up2(unsigned long long v) {
    float2 r; asm("mov.b64 {%0, %1}, %2;" : "=f"(r.x), "=f"(r.y) : "l"(v)); return r;
}

// Two tanh's through one MUFU op: f32 pair -> f16x2 -> tanh.approx.f16x2 -> f32 pair
__device__ __forceinline__ void tanh2_h(float x0, float x1, float &t0, float &t1) {
    unsigned hx, th;
    unsigned short lo, hi;
    asm("cvt.rn.f16x2.f32 %0, %1, %2;" : "=r"(hx) : "f"(x1), "f"(x0));  // low=x0, high=x1
    asm("tanh.approx.f16x2 %0, %1;" : "=r"(th) : "r"(hx));
    asm("mov.b32 {%0, %1}, %2;" : "=h"(lo), "=h"(hi) : "r"(th));
    asm("cvt.f32.f16 %0, %1;" : "=f"(t0) : "h"(lo));
    asm("cvt.f32.f16 %0, %1;" : "=f"(t1) : "h"(hi));
}

// ---------------------------------------------------------------------------
// Combined projection GEMM: 256 blocks (128 for q, 128 for kT).
// 64x64 tile, 256 threads, 4x4 micro-tile, f32x2 FMAs, double-buffered. (R6)
// ---------------------------------------------------------------------------
__global__ __launch_bounds__(256) void proj_kernel(const float* __restrict__ query,
                                                   const float* __restrict__ key,
                                                   const float* __restrict__ Wq,
                                                   const float* __restrict__ Wk)
{
    __shared__ __align__(16) float As[16][68];
    __shared__ __align__(16) float Bs[16][64];

    int bid = blockIdx.x;
    int is_k = bid >> 7;
    int local = bid & 127;
    int row0 = (local >> 2) * 64;
    int col0 = (local & 3) * 64;
    const float* A = is_k ? key : query;
    const float* B = is_k ? Wk : Wq;

    int t = threadIdx.x;
    int tx = t & 15, ty = t >> 4;
    int arow = t >> 2, akq = t & 3;
    int bk = t >> 4, bh = t & 15;

    const float* Aptr = A + (row0 + arow) * DDv + akq * 4;
    const float* Bptr = B + bk * HHv + col0 + bh * 4;

    unsigned long long acc[4][2];
#pragma unroll
    for (int i = 0; i < 4; i++) { acc[i][0] = 0ull; acc[i][1] = 0ull; }

    float4 a_n = *(const float4*)(Aptr);
    float4 b_n = *(const float4*)(Bptr);

    for (int k0 = 0; k0 < DDv; k0 += 16) {
        As[akq * 4 + 0][arow] = a_n.x;
        As[akq * 4 + 1][arow] = a_n.y;
        As[akq * 4 + 2][arow] = a_n.z;
        As[akq * 4 + 3][arow] = a_n.w;
        *(float4*)&Bs[bk][bh * 4] = b_n;
        __syncthreads();

        if (k0 + 16 < DDv) {
            a_n = *(const float4*)(Aptr + k0 + 16);
            b_n = *(const float4*)(Bptr + (k0 + 16) * HHv);
        }

#pragma unroll
        for (int k = 0; k < 16; k++) {
            const unsigned long long* br = (const unsigned long long*)&Bs[k][tx * 4];
            unsigned long long b0 = br[0], b1 = br[1];
#pragma unroll
            for (int i = 0; i < 4; i++) {
                float a = As[k][ty * 4 + i];
                unsigned long long aa = pk2(a, a);
                fma2(acc[i][0], aa, b0);
                fma2(acc[i][1], aa, b1);
            }
        }
        __syncthreads();
    }

#pragma unroll
    for (int i = 0; i < 4; i++) {
        int row = row0 + ty * 4 + i;
        int col = col0 + tx * 4;
        float2 c0 = up2(acc[i][0]);
        float2 c1 = up2(acc[i][1]);
        if (!is_k) {
            *(float4*)(g_q + row * HHv + col) = make_float4(c0.x, c0.y, c1.x, c1.y);
        } else {
            int bb = row >> 9, m = row & 511;
            float* base = g_kT + (bb * HHv) * MMv + m;
            base[(col + 0) * MMv] = c0.x;
            base[(col + 1) * MMv] = c0.y;
            base[(col + 2) * MMv] = c1.x;
            base[(col + 3) * MMv] = c1.y;
        }
    }
}

// ---------------------------------------------------------------------------
// Score kernel: sc[b,n,m] = sum_h w[h] * tanh(q[b,n,h] + k[b,m,h])
// Tile (8q x 128m), 128 threads, grid 1024 (lean footprint = high occupancy).
// Inner loop now evaluates tanh two-at-a-time via tanh.approx.f16x2:
// MUFU ops halved (4 cyc/elem), expected issue/cvt-bound ~5 cyc/elem.
// ---------------------------------------------------------------------------
__global__ __launch_bounds__(128) void score_kernel(const float* __restrict__ Wv)
{
    __shared__ __align__(16) float qs[8][264];  // [q][h]
    __shared__ __align__(16) float ws[HHv];

    int t = threadIdx.x;
    int bid = blockIdx.x;
    int mc = bid & 3;
    int qc = (bid >> 2) & 63;
    int b = bid >> 8;
    int n0 = qc * 8;
    int m = mc * 128 + t;

    // Stage 8 projected-q rows + W_v into smem
#pragma unroll
    for (int r = 0; r < 4; r++) {
        int idx = t + r * 128;
        int q = idx >> 6, c4 = idx & 63;
        float4 v = ((const float4*)(g_q + (b * NQv + n0 + q) * HHv))[c4];
        *(float4*)&qs[q][c4 * 4] = v;
    }
    if (t < 64) ((float4*)ws)[t] = ((const float4*)Wv)[t];
    __syncthreads();

    float acc[8];
#pragma unroll
    for (int q = 0; q < 8; q++) acc[q] = 0.f;

    const float* kb = g_kT + (b * HHv) * MMv + m;
#pragma unroll 4
    for (int h = 0; h < HHv; h++) {
        float kv = kb[h * MMv];
        float wv = ws[h];
#pragma unroll
        for (int p = 0; p < 4; p++) {
            float x0 = qs[2 * p + 0][h] + kv;
            float x1 = qs[2 * p + 1][h] + kv;
            float t0, t1;
            tanh2_h(x0, x1, t0, t1);
            acc[2 * p + 0] = fmaf(wv, t0, acc[2 * p + 0]);
            acc[2 * p + 1] = fmaf(wv, t1, acc[2 * p + 1]);
        }
    }

#pragma unroll
    for (int q = 0; q < 8; q++)
        g_sc[(b * NQv + n0 + q) * MMv + m] = acc[q];
}

// ---------------------------------------------------------------------------
// Softmax + AV (R3/R6-proven): out = softmax_m(sc) @ value. Grid 256 x 256thr.
// ---------------------------------------------------------------------------
__global__ __launch_bounds__(256) void softav_kernel(const float* __restrict__ value,
                                                     float* __restrict__ out)
{
    __shared__ __align__(16) float sc[8][MMv];
    __shared__ __align__(16) float2 ps[2][8][128];
    __shared__ float inv_s[8];

    int t = threadIdx.x;
    int b = (int)(blockIdx.x >> 6);
    int n0 = ((int)blockIdx.x & 63) << 3;
    int w = t >> 5, lane = t & 31;

    {
        const float* srow = g_sc + (b * NQv + n0 + w) * MMv;
        float vals[16];
        float vmax = -1e30f;
#pragma unroll
        for (int j = 0; j < 16; j++) {
            vals[j] = srow[lane + j * 32];
            vmax = fmaxf(vmax, vals[j]);
        }
#pragma unroll
        for (int o = 16; o > 0; o >>= 1)
            vmax = fmaxf(vmax, __shfl_xor_sync(0xffffffffu, vmax, o));
        float sum = 0.f;
#pragma unroll
        for (int j = 0; j < 16; j++) {
            float p = fex2((vals[j] - vmax) * 1.4426950408889634f);
            sc[w][lane + j * 32] = p;
            sum += p;
        }
#pragma unroll
        for (int o = 16; o > 0; o >>= 1)
            sum += __shfl_xor_sync(0xffffffffu, sum, o);
        if (lane == 0) inv_s[w] = 1.0f / sum;
    }
    __syncthreads();

    int mg = t >> 7;
    int vg = t & 127;
    const float* vbase = value + (b * MMv + mg * 256) * DDv + vg * 2;
    unsigned long long acc[8];
#pragma unroll
    for (int q = 0; q < 8; q++) acc[q] = 0ull;
#pragma unroll 4
    for (int mm = 0; mm < 256; mm++) {
        float2 vv = *(const float2*)(vbase + mm * DDv);
        unsigned long long v2 = pk2(vv.x, vv.y);
        int mIdx = mg * 256 + mm;
#pragma unroll
        for (int q = 0; q < 8; q++) {
            float a = sc[q][mIdx];
            fma2(acc[q], pk2(a, a), v2);
        }
    }
#pragma unroll
    for (int q = 0; q < 8; q++) ps[mg][q][vg] = up2(acc[q]);
    __syncthreads();

#pragma unroll
    for (int r = 0; r < 4; r++) {
        int p = t + r * 256;
        int q = p >> 7, v2i = p & 127;
        float2 s0 = ps[0][q][v2i], s1 = ps[1][q][v2i];
        float iv = inv_s[q];
        float2 o = make_float2((s0.x + s1.x) * iv, (s0.y + s1.y) * iv);
        ((float2*)out)[(b * NQv + n0 + q) * 128 + v2i] = o;
    }
}

extern "C" void kernel_launch(void* const* d_in, const int* in_sizes, int n_in,
                              void* d_out, int out_size)
{
    const float* query = (const float*)d_in[0];
    const float* key   = (const float*)d_in[1];
    const float* value = (const float*)d_in[2];
    const float* Wq    = (const float*)d_in[3];
    const float* Wk    = (const float*)d_in[4];
    const float* Wv    = (const float*)d_in[5];
    float* out = (float*)d_out;

    proj_kernel<<<256, 256>>>(query, key, Wq, Wk);
    score_kernel<<<1024, 128>>>(Wv);
    softav_kernel<<<256, 256>>>(value, out);
}

// round 8
// speedup vs baseline: 1.0211x; 1.0211x over previous
#include <cuda_runtime.h>

// Fixed problem dims
#define NB 4
#define NQv 512
#define MMv 512
#define DDv 256
#define HHv 256

// Scratch (device globals: no allocations allowed)
__device__ float g_q[NB * NQv * HHv];    // projected q, [b*NQ+n][h]
__device__ float g_kT[NB * HHv * MMv];   // projected k, transposed: [b][h][m]
__device__ float g_sc[NB * NQv * MMv];   // raw scores [b][n][m]

__device__ __forceinline__ float ftanh(float x) {
    float y; asm("tanh.approx.f32 %0, %1;" : "=f"(y) : "f"(x)); return y;
}
__device__ __forceinline__ float fex2(float x) {
    float y; asm("ex2.approx.f32 %0, %1;" : "=f"(y) : "f"(x)); return y;
}
__device__ __forceinline__ unsigned long long pk2(float a, float b) {
    unsigned long long r; asm("mov.b64 %0, {%1, %2};" : "=l"(r) : "f"(a), "f"(b)); return r;
}
__device__ __forceinline__ void fma2(unsigned long long &d, unsigned long long a, unsigned long long b) {
    asm("fma.rn.f32x2 %0, %1, %2, %0;" : "+l"(d) : "l"(a), "l"(b));
}
__device__ __forceinline__ float2 up2(unsigned long long v) {
    float2 r; asm("mov.b64 {%0, %1}, %2;" : "=f"(r.x), "=f"(r.y) : "l"(v)); return r;
}
// pack two f32 into f16x2
__device__ __forceinline__ unsigned packh2(float lo, float hi) {
    unsigned r; asm("cvt.rn.f16x2.f32 %0, %1, %2;" : "=r"(r) : "f"(hi), "f"(lo)); return r;
}
__device__ __forceinline__ unsigned hadd2(unsigned a, unsigned b) {
    unsigned r; asm("add.f16x2 %0, %1, %2;" : "=r"(r) : "r"(a), "r"(b)); return r;
}
__device__ __forceinline__ unsigned htanh2(unsigned a) {
    unsigned r; asm("tanh.approx.f16x2 %0, %1;" : "=r"(r) : "r"(a)); return r;
}
__device__ __forceinline__ void unp2(unsigned p, float &f0, float &f1) {
    unsigned short lo, hi;
    asm("mov.b32 {%0, %1}, %2;" : "=h"(lo), "=h"(hi) : "r"(p));
    asm("cvt.f32.f16 %0, %1;" : "=f"(f0) : "h"(lo));
    asm("cvt.f32.f16 %0, %1;" : "=f"(f1) : "h"(hi));
}

// ---------------------------------------------------------------------------
// Combined projection GEMM (R6-proven, frozen): 256 blocks, 64x64 tile,
// 4x4 micro-tile, f32x2 FMAs, double-buffered.
// ---------------------------------------------------------------------------
__global__ __launch_bounds__(256) void proj_kernel(const float* __restrict__ query,
                                                   const float* __restrict__ key,
                                                   const float* __restrict__ Wq,
                                                   const float* __restrict__ Wk)
{
    __shared__ __align__(16) float As[16][68];
    __shared__ __align__(16) float Bs[16][64];

    int bid = blockIdx.x;
    int is_k = bid >> 7;
    int local = bid & 127;
    int row0 = (local >> 2) * 64;
    int col0 = (local & 3) * 64;
    const float* A = is_k ? key : query;
    const float* B = is_k ? Wk : Wq;

    int t = threadIdx.x;
    int tx = t & 15, ty = t >> 4;
    int arow = t >> 2, akq = t & 3;
    int bk = t >> 4, bh = t & 15;

    const float* Aptr = A + (row0 + arow) * DDv + akq * 4;
    const float* Bptr = B + bk * HHv + col0 + bh * 4;

    unsigned long long acc[4][2];
#pragma unroll
    for (int i = 0; i < 4; i++) { acc[i][0] = 0ull; acc[i][1] = 0ull; }

    float4 a_n = *(const float4*)(Aptr);
    float4 b_n = *(const float4*)(Bptr);

    for (int k0 = 0; k0 < DDv; k0 += 16) {
        As[akq * 4 + 0][arow] = a_n.x;
        As[akq * 4 + 1][arow] = a_n.y;
        As[akq * 4 + 2][arow] = a_n.z;
        As[akq * 4 + 3][arow] = a_n.w;
        *(float4*)&Bs[bk][bh * 4] = b_n;
        __syncthreads();

        if (k0 + 16 < DDv) {
            a_n = *(const float4*)(Aptr + k0 + 16);
            b_n = *(const float4*)(Bptr + (k0 + 16) * HHv);
        }

#pragma unroll
        for (int k = 0; k < 16; k++) {
            const unsigned long long* br = (const unsigned long long*)&Bs[k][tx * 4];
            unsigned long long b0 = br[0], b1 = br[1];
#pragma unroll
            for (int i = 0; i < 4; i++) {
                float a = As[k][ty * 4 + i];
                unsigned long long aa = pk2(a, a);
                fma2(acc[i][0], aa, b0);
                fma2(acc[i][1], aa, b1);
            }
        }
        __syncthreads();
    }

#pragma unroll
    for (int i = 0; i < 4; i++) {
        int row = row0 + ty * 4 + i;
        int col = col0 + tx * 4;
        float2 c0 = up2(acc[i][0]);
        float2 c1 = up2(acc[i][1]);
        if (!is_k) {
            *(float4*)(g_q + row * HHv + col) = make_float4(c0.x, c0.y, c1.x, c1.y);
        } else {
            int bb = row >> 9, m = row & 511;
            float* base = g_kT + (bb * HHv) * MMv + m;
            base[(col + 0) * MMv] = c0.x;
            base[(col + 1) * MMv] = c0.y;
            base[(col + 2) * MMv] = c1.x;
            base[(col + 3) * MMv] = c1.y;
        }
    }
}

// ---------------------------------------------------------------------------
// Score kernel, pipe-balanced: per h, q0/q1 via f32 MUFU.TANH, q2..q7 via
// three tanh.approx.f16x2. Balances MUFU (~5.0 cyc/elem) vs FMA (~5.75).
// q staged per-h as {float2 (f32 path), 4x f16x2 (packed pairs)} -> only
// 2 broadcast LDS per h. Tile (8q x 128m), 128 threads, grid 1024.
// ---------------------------------------------------------------------------
__global__ __launch_bounds__(128) void score_kernel(const float* __restrict__ Wv)
{
    __shared__ __align__(16) float2 qsf[HHv];      // q0,q1 per h           (2KB)
    __shared__ __align__(16) uint4 qsh[HHv];       // (q2,q3)(q4,q5)(q6,q7) (4KB)
    __shared__ __align__(16) float ws[HHv];        //                       (1KB)

    int t = threadIdx.x;
    int bid = blockIdx.x;
    int mc = bid & 3;
    int qc = (bid >> 2) & 63;
    int b = bid >> 8;
    int n0 = qc * 8;
    int m = mc * 128 + t;

    // Stage q: thread t covers h = {2t, 2t+1}; read float2 from each q row.
    {
        const float* qb = g_q + (b * NQv + n0) * HHv + 2 * t;
        float2 r[8];
#pragma unroll
        for (int q = 0; q < 8; q++)
            r[q] = *(const float2*)(qb + q * HHv);
#pragma unroll
        for (int j = 0; j < 2; j++) {
            int h = 2 * t + j;
            float v[8] = { j ? r[0].y : r[0].x, j ? r[1].y : r[1].x,
                           j ? r[2].y : r[2].x, j ? r[3].y : r[3].x,
                           j ? r[4].y : r[4].x, j ? r[5].y : r[5].x,
                           j ? r[6].y : r[6].x, j ? r[7].y : r[7].x };
            qsf[h] = make_float2(v[0], v[1]);
            qsh[h] = make_uint4(packh2(v[2], v[3]), packh2(v[4], v[5]),
                                packh2(v[6], v[7]), 0u);
        }
    }
    if (t < 64) ((float4*)ws)[t] = ((const float4*)Wv)[t];
    __syncthreads();

    float acc[8];
#pragma unroll
    for (int q = 0; q < 8; q++) acc[q] = 0.f;

    const float* kb = g_kT + (b * HHv) * MMv + m;
#pragma unroll 4
    for (int h = 0; h < HHv; h++) {
        float kv = kb[h * MMv];
        float wv = ws[h];

        // f32 path: q0, q1
        float2 qf = qsf[h];
        acc[0] = fmaf(wv, ftanh(qf.x + kv), acc[0]);
        acc[1] = fmaf(wv, ftanh(qf.y + kv), acc[1]);

        // f16x2 path: q2..q7 (3 pairs)
        uint4 qh = qsh[h];
        unsigned kk2 = packh2(kv, kv);
        unsigned p0 = htanh2(hadd2(qh.x, kk2));
        unsigned p1 = htanh2(hadd2(qh.y, kk2));
        unsigned p2 = htanh2(hadd2(qh.z, kk2));
        float t0, t1;
        unp2(p0, t0, t1);
        acc[2] = fmaf(wv, t0, acc[2]);
        acc[3] = fmaf(wv, t1, acc[3]);
        unp2(p1, t0, t1);
        acc[4] = fmaf(wv, t0, acc[4]);
        acc[5] = fmaf(wv, t1, acc[5]);
        unp2(p2, t0, t1);
        acc[6] = fmaf(wv, t0, acc[6]);
        acc[7] = fmaf(wv, t1, acc[7]);
    }

#pragma unroll
    for (int q = 0; q < 8; q++)
        g_sc[(b * NQv + n0 + q) * MMv + m] = acc[q];
}

// ---------------------------------------------------------------------------
// Softmax + AV (R3/R6-proven, frozen): out = softmax_m(sc) @ value.
// ---------------------------------------------------------------------------
__global__ __launch_bounds__(256) void softav_kernel(const float* __restrict__ value,
                                                     float* __restrict__ out)
{
    __shared__ __align__(16) float sc[8][MMv];
    __shared__ __align__(16) float2 ps[2][8][128];
    __shared__ float inv_s[8];

    int t = threadIdx.x;
    int b = (int)(blockIdx.x >> 6);
    int n0 = ((int)blockIdx.x & 63) << 3;
    int w = t >> 5, lane = t & 31;

    {
        const float* srow = g_sc + (b * NQv + n0 + w) * MMv;
        float vals[16];
        float vmax = -1e30f;
#pragma unroll
        for (int j = 0; j < 16; j++) {
            vals[j] = srow[lane + j * 32];
            vmax = fmaxf(vmax, vals[j]);
        }
#pragma unroll
        for (int o = 16; o > 0; o >>= 1)
            vmax = fmaxf(vmax, __shfl_xor_sync(0xffffffffu, vmax, o));
        float sum = 0.f;
#pragma unroll
        for (int j = 0; j < 16; j++) {
            float p = fex2((vals[j] - vmax) * 1.4426950408889634f);
            sc[w][lane + j * 32] = p;
            sum += p;
        }
#pragma unroll
        for (int o = 16; o > 0; o >>= 1)
            sum += __shfl_xor_sync(0xffffffffu, sum, o);
        if (lane == 0) inv_s[w] = 1.0f / sum;
    }
    __syncthreads();

    int mg = t >> 7;
    int vg = t & 127;
    const float* vbase = value + (b * MMv + mg * 256) * DDv + vg * 2;
    unsigned long long acc[8];
#pragma unroll
    for (int q = 0; q < 8; q++) acc[q] = 0ull;
#pragma unroll 4
    for (int mm = 0; mm < 256; mm++) {
        float2 vv = *(const float2*)(vbase + mm * DDv);
        unsigned long long v2 = pk2(vv.x, vv.y);
        int mIdx = mg * 256 + mm;
#pragma unroll
        for (int q = 0; q < 8; q++) {
            float a = sc[q][mIdx];
            fma2(acc[q], pk2(a, a), v2);
        }
    }
#pragma unroll
    for (int q = 0; q < 8; q++) ps[mg][q][vg] = up2(acc[q]);
    __syncthreads();

#pragma unroll
    for (int r = 0; r < 4; r++) {
        int p = t + r * 256;
        int q = p >> 7, v2i = p & 127;
        float2 s0 = ps[0][q][v2i], s1 = ps[1][q][v2i];
        float iv = inv_s[q];
        float2 o = make_float2((s0.x + s1.x) * iv, (s0.y + s1.y) * iv);
        ((float2*)out)[(b * NQv + n0 + q) * 128 + v2i] = o;
    }
}

extern "C" void kernel_launch(void* const* d_in, const int* in_sizes, int n_in,
                              void* d_out, int out_size)
{
    const float* query = (const float*)d_in[0];
    const float* key   = (const float*)d_in[1];
    const float* value = (const float*)d_in[2];
    const float* Wq    = (const float*)d_in[3];
    const float* Wk    = (const float*)d_in[4];
    const float* Wv    = (const float*)d_in[5];
    float* out = (float*)d_out;

    proj_kernel<<<256, 256>>>(query, key, Wq, Wk);
    score_kernel<<<1024, 128>>>(Wv);
    softav_kernel<<<256, 256>>>(value, out);
}

// round 9
// speedup vs baseline: 1.0247x; 1.0035x over previous
#include <cuda_runtime.h>

// Fixed problem dims
#define NB 4
#define NQv 512
#define MMv 512
#define DDv 256
#define HHv 256

// Scratch (device globals: no allocations allowed)
__device__ float    g_q[NB * NQv * HHv];     // projected q, [b*NQ+n][h]
__device__ unsigned g_kTh[NB * HHv * MMv];   // projected k, transposed, packed half2(k,k)
__device__ float    g_sc[NB * NQv * MMv];    // raw scores [b][n][m]

__device__ __forceinline__ float fex2(float x) {
    float y; asm("ex2.approx.f32 %0, %1;" : "=f"(y) : "f"(x)); return y;
}
__device__ __forceinline__ unsigned long long pk2(float a, float b) {
    unsigned long long r; asm("mov.b64 %0, {%1, %2};" : "=l"(r) : "f"(a), "f"(b)); return r;
}
__device__ __forceinline__ void fma2(unsigned long long &d, unsigned long long a, unsigned long long b) {
    asm("fma.rn.f32x2 %0, %1, %2, %0;" : "+l"(d) : "l"(a), "l"(b));
}
__device__ __forceinline__ float2 up2(unsigned long long v) {
    float2 r; asm("mov.b64 {%0, %1}, %2;" : "=f"(r.x), "=f"(r.y) : "l"(v)); return r;
}
__device__ __forceinline__ unsigned packh2(float lo, float hi) {
    unsigned r; asm("cvt.rn.f16x2.f32 %0, %1, %2;" : "=r"(r) : "f"(hi), "f"(lo)); return r;
}
__device__ __forceinline__ unsigned hadd2(unsigned a, unsigned b) {
    unsigned r; asm("add.f16x2 %0, %1, %2;" : "=r"(r) : "r"(a), "r"(b)); return r;
}
__device__ __forceinline__ unsigned htanh2(unsigned a) {
    unsigned r; asm("tanh.approx.f16x2 %0, %1;" : "=r"(r) : "r"(a)); return r;
}
__device__ __forceinline__ unsigned hfma2(unsigned a, unsigned b, unsigned c) {
    unsigned r; asm("fma.rn.f16x2 %0, %1, %2, %3;" : "=r"(r) : "r"(a), "r"(b), "r"(c)); return r;
}
__device__ __forceinline__ void drain2(unsigned p, float &f0, float &f1) {
    unsigned short lo, hi; float a, b;
    asm("mov.b32 {%0, %1}, %2;" : "=h"(lo), "=h"(hi) : "r"(p));
    asm("cvt.f32.f16 %0, %1;" : "=f"(a) : "h"(lo));
    asm("cvt.f32.f16 %0, %1;" : "=f"(b) : "h"(hi));
    f0 += a; f1 += b;
}

// ---------------------------------------------------------------------------
// Combined projection GEMM: 256 blocks (128 q, 128 k). 64x64 tile, 256 thr,
// 4x4 micro-tile, f32x2 FMAs, double-buffered. k output written directly as
// packed half2(k,k) -> score kernel needs no per-element conversion.
// ---------------------------------------------------------------------------
__global__ __launch_bounds__(256) void proj_kernel(const float* __restrict__ query,
                                                   const float* __restrict__ key,
                                                   const float* __restrict__ Wq,
                                                   const float* __restrict__ Wk)
{
    __shared__ __align__(16) float As[16][68];
    __shared__ __align__(16) float Bs[16][64];

    int bid = blockIdx.x;
    int is_k = bid >> 7;
    int local = bid & 127;
    int row0 = (local >> 2) * 64;
    int col0 = (local & 3) * 64;
    const float* A = is_k ? key : query;
    const float* B = is_k ? Wk : Wq;

    int t = threadIdx.x;
    int tx = t & 15, ty = t >> 4;
    int arow = t >> 2, akq = t & 3;
    int bk = t >> 4, bh = t & 15;

    const float* Aptr = A + (row0 + arow) * DDv + akq * 4;
    const float* Bptr = B + bk * HHv + col0 + bh * 4;

    unsigned long long acc[4][2];
#pragma unroll
    for (int i = 0; i < 4; i++) { acc[i][0] = 0ull; acc[i][1] = 0ull; }

    float4 a_n = *(const float4*)(Aptr);
    float4 b_n = *(const float4*)(Bptr);

    for (int k0 = 0; k0 < DDv; k0 += 16) {
        As[akq * 4 + 0][arow] = a_n.x;
        As[akq * 4 + 1][arow] = a_n.y;
        As[akq * 4 + 2][arow] = a_n.z;
        As[akq * 4 + 3][arow] = a_n.w;
        *(float4*)&Bs[bk][bh * 4] = b_n;
        __syncthreads();

        if (k0 + 16 < DDv) {
            a_n = *(const float4*)(Aptr + k0 + 16);
            b_n = *(const float4*)(Bptr + (k0 + 16) * HHv);
        }

#pragma unroll
        for (int k = 0; k < 16; k++) {
            const unsigned long long* br = (const unsigned long long*)&Bs[k][tx * 4];
            unsigned long long b0 = br[0], b1 = br[1];
#pragma unroll
            for (int i = 0; i < 4; i++) {
                float a = As[k][ty * 4 + i];
                unsigned long long aa = pk2(a, a);
                fma2(acc[i][0], aa, b0);
                fma2(acc[i][1], aa, b1);
            }
        }
        __syncthreads();
    }

#pragma unroll
    for (int i = 0; i < 4; i++) {
        int row = row0 + ty * 4 + i;
        int col = col0 + tx * 4;
        float2 c0 = up2(acc[i][0]);
        float2 c1 = up2(acc[i][1]);
        if (!is_k) {
            *(float4*)(g_q + row * HHv + col) = make_float4(c0.x, c0.y, c1.x, c1.y);
        } else {
            int bb = row >> 9, m = row & 511;
            unsigned* base = g_kTh + (bb * HHv) * MMv + m;
            base[(col + 0) * MMv] = packh2(c0.x, c0.x);
            base[(col + 1) * MMv] = packh2(c0.y, c0.y);
            base[(col + 2) * MMv] = packh2(c1.x, c1.x);
            base[(col + 3) * MMv] = packh2(c1.y, c1.y);
        }
    }
}

// ---------------------------------------------------------------------------
// Score kernel, all-f16x2 datapath: per h = 4 x (HADD2 + TANH2.f16x2 + HFMA2),
// zero conversions in the loop; f16 partials drained to f32 every 8 h.
// XU/h = 4 tanh2 (32cyc) + drain (~4cyc) -> predicted ~35-40us.
// Tile (8q x 128m), 128 threads, grid 1024 (lean smem 5KB = high occupancy).
// ---------------------------------------------------------------------------
__global__ __launch_bounds__(128) void score_kernel(const float* __restrict__ Wv)
{
    __shared__ __align__(16) uint4 qsh[HHv];       // 4 q-pairs per h (4KB)
    __shared__ __align__(16) unsigned wsh[HHv];    // (w,w) per h     (1KB)

    int t = threadIdx.x;
    int bid = blockIdx.x;
    int mc = bid & 3;
    int qc = (bid >> 2) & 63;
    int b = bid >> 8;
    int n0 = qc * 8;
    int m = mc * 128 + t;

    // Stage q as f16x2 pairs: thread t covers h = {2t, 2t+1}
    {
        const float* qb = g_q + (b * NQv + n0) * HHv + 2 * t;
        float2 r[8];
#pragma unroll
        for (int q = 0; q < 8; q++)
            r[q] = *(const float2*)(qb + q * HHv);
#pragma unroll
        for (int j = 0; j < 2; j++) {
            int h = 2 * t + j;
            float v0 = j ? r[0].y : r[0].x, v1 = j ? r[1].y : r[1].x;
            float v2 = j ? r[2].y : r[2].x, v3 = j ? r[3].y : r[3].x;
            float v4 = j ? r[4].y : r[4].x, v5 = j ? r[5].y : r[5].x;
            float v6 = j ? r[6].y : r[6].x, v7 = j ? r[7].y : r[7].x;
            qsh[h] = make_uint4(packh2(v0, v1), packh2(v2, v3),
                                packh2(v4, v5), packh2(v6, v7));
        }
        // w packed (w,w)
        float2 wv = *(const float2*)(Wv + 2 * t);
        wsh[2 * t + 0] = packh2(wv.x, wv.x);
        wsh[2 * t + 1] = packh2(wv.y, wv.y);
    }
    __syncthreads();

    float facc[8];
#pragma unroll
    for (int q = 0; q < 8; q++) facc[q] = 0.f;

    const unsigned* kb = g_kTh + (b * HHv) * MMv + m;

    for (int h0 = 0; h0 < HHv; h0 += 8) {
        unsigned acc2[4] = {0u, 0u, 0u, 0u};
#pragma unroll
        for (int hh = 0; hh < 8; hh++) {
            int h = h0 + hh;
            unsigned kk2 = kb[h * MMv];
            uint4 qh = qsh[h];
            unsigned w2 = wsh[h];
            acc2[0] = hfma2(w2, htanh2(hadd2(qh.x, kk2)), acc2[0]);
            acc2[1] = hfma2(w2, htanh2(hadd2(qh.y, kk2)), acc2[1]);
            acc2[2] = hfma2(w2, htanh2(hadd2(qh.z, kk2)), acc2[2]);
            acc2[3] = hfma2(w2, htanh2(hadd2(qh.w, kk2)), acc2[3]);
        }
        drain2(acc2[0], facc[0], facc[1]);
        drain2(acc2[1], facc[2], facc[3]);
        drain2(acc2[2], facc[4], facc[5]);
        drain2(acc2[3], facc[6], facc[7]);
    }

#pragma unroll
    for (int q = 0; q < 8; q++)
        g_sc[(b * NQv + n0 + q) * MMv + m] = facc[q];
}

// ---------------------------------------------------------------------------
// Softmax + AV (R3/R6-proven, frozen): out = softmax_m(sc) @ value.
// ---------------------------------------------------------------------------
__global__ __launch_bounds__(256) void softav_kernel(const float* __restrict__ value,
                                                     float* __restrict__ out)
{
    __shared__ __align__(16) float sc[8][MMv];
    __shared__ __align__(16) float2 ps[2][8][128];
    __shared__ float inv_s[8];

    int t = threadIdx.x;
    int b = (int)(blockIdx.x >> 6);
    int n0 = ((int)blockIdx.x & 63) << 3;
    int w = t >> 5, lane = t & 31;

    {
        const float* srow = g_sc + (b * NQv + n0 + w) * MMv;
        float vals[16];
        float vmax = -1e30f;
#pragma unroll
        for (int j = 0; j < 16; j++) {
            vals[j] = srow[lane + j * 32];
            vmax = fmaxf(vmax, vals[j]);
        }
#pragma unroll
        for (int o = 16; o > 0; o >>= 1)
            vmax = fmaxf(vmax, __shfl_xor_sync(0xffffffffu, vmax, o));
        float sum = 0.f;
#pragma unroll
        for (int j = 0; j < 16; j++) {
            float p = fex2((vals[j] - vmax) * 1.4426950408889634f);
            sc[w][lane + j * 32] = p;
            sum += p;
        }
#pragma unroll
        for (int o = 16; o > 0; o >>= 1)
            sum += __shfl_xor_sync(0xffffffffu, sum, o);
        if (lane == 0) inv_s[w] = 1.0f / sum;
    }
    __syncthreads();

    int mg = t >> 7;
    int vg = t & 127;
    const float* vbase = value + (b * MMv + mg * 256) * DDv + vg * 2;
    unsigned long long acc[8];
#pragma unroll
    for (int q = 0; q < 8; q++) acc[q] = 0ull;
#pragma unroll 4
    for (int mm = 0; mm < 256; mm++) {
        float2 vv = *(const float2*)(vbase + mm * DDv);
        unsigned long long v2 = pk2(vv.x, vv.y);
        int mIdx = mg * 256 + mm;
#pragma unroll
        for (int q = 0; q < 8; q++) {
            float a = sc[q][mIdx];
            fma2(acc[q], pk2(a, a), v2);
        }
    }
#pragma unroll
    for (int q = 0; q < 8; q++) ps[mg][q][vg] = up2(acc[q]);
    __syncthreads();

#pragma unroll
    for (int r = 0; r < 4; r++) {
        int p = t + r * 256;
        int q = p >> 7, v2i = p & 127;
        float2 s0 = ps[0][q][v2i], s1 = ps[1][q][v2i];
        float iv = inv_s[q];
        float2 o = make_float2((s0.x + s1.x) * iv, (s0.y + s1.y) * iv);
        ((float2*)out)[(b * NQv + n0 + q) * 128 + v2i] = o;
    }
}

extern "C" void kernel_launch(void* const* d_in, const int* in_sizes, int n_in,
                              void* d_out, int out_size)
{
    const float* query = (const float*)d_in[0];
    const float* key   = (const float*)d_in[1];
    const float* value = (const float*)d_in[2];
    const float* Wq    = (const float*)d_in[3];
    const float* Wk    = (const float*)d_in[4];
    const float* Wv    = (const float*)d_in[5];
    float* out = (float*)d_out;

    proj_kernel<<<256, 256>>>(query, key, Wq, Wk);
    score_kernel<<<1024, 128>>>(Wv);
    softav_kernel<<<256, 256>>>(value, out);
}